// round 15
// baseline (speedup 1.0000x reference)
#include <cuda_runtime.h>
#include <cuda_fp16.h>
#include <cstdint>

// ---------------------------------------------------------------------------
// GumbelSoftmaxModule4 v15: v14 + GEMM1 warps widened in m (32 rows x 16
// codes/chunk). B-GEMM1 fragments per warp halve (256 -> 128). Codes
// re-labeled so each thread's 4 probs/chunk-row are consecutive (float4
// gumbel/csq). sP word invariant preserved -> GEMM2/avg unchanged.
// ---------------------------------------------------------------------------

namespace {
constexpr int KQ = 512, NG = 4, SDQ = 128, BQ = 16, TQ = 2048;
constexpr int NTOK = BQ * TQ;            // 32768
constexpr int TM   = 64;                 // tokens per CTA
constexpr int NTHR = 256;                // 8 warps
constexpr int PSW  = 272;                // sP row stride (uint32 words)
constexpr int SXS  = 68;                 // X / stage row stride (f32)
constexpr int OFF_P   = 0;                          // sP: 64*272*4 = 69632
constexpr int OFF_CSQ = 69632;                      // 512 f32 (pre-scaled)
constexpr int OFF_RS  = OFF_CSQ + 2048;             // 64 f32
constexpr int OFF_RI  = OFF_RS + 256;               // 64 f32
constexpr int SMEM_BYTES = OFF_RI + 256;            // 72192 -> occ 2
constexpr int QUANT_ELEMS = BQ * 512 * TQ;
constexpr float L2E  = 1.4426950408889634f;
constexpr float HL2E = 0.7213475204444817f;
}

__device__ float g_csq[NG * KQ];
__device__ float g_avg[NG * KQ];
__device__ unsigned int g_ctr;
// fragment-major: [g][frag 0..255][128 words]; frag = 512B = one warp LDG.128
__device__ __align__(16) uint32_t g_w1f[NG * 256 * 128];
__device__ __align__(16) uint32_t g_wtf[NG * 256 * 128];

// ------------------------------ helpers ------------------------------------
__device__ __forceinline__ int inv16(int o) {      // GEMM1 d-interleave only
    return (((o >> 1) & 1) << 4) | ((o & 1) << 3) | (((o >> 2) & 3) << 1);
}
__device__ __forceinline__ uint32_t pk(float lo, float hi) {
    __half2 h = __floats2half2_rn(lo, hi);
    return *reinterpret_cast<uint32_t*>(&h);
}
__device__ __forceinline__ float ex2(float y) {    // 2^y via MUFU
    float r;
    asm("ex2.approx.f32 %0, %1;" : "=f"(r) : "f"(y));
    return r;
}
__device__ __forceinline__ void mma_f16(float* c,
                                        uint32_t a0, uint32_t a1, uint32_t a2, uint32_t a3,
                                        uint32_t b0, uint32_t b1) {
    asm volatile(
        "mma.sync.aligned.m16n8k16.row.col.f32.f16.f16.f32 "
        "{%0,%1,%2,%3}, {%4,%5,%6,%7}, {%8,%9}, {%0,%1,%2,%3};\n"
        : "+f"(c[0]), "+f"(c[1]), "+f"(c[2]), "+f"(c[3])
        : "r"(a0), "r"(a1), "r"(a2), "r"(a3), "r"(b0), "r"(b1));
}
__device__ __forceinline__ const float* pick_w(const float* w0, const float* w1,
                                               const float* w2, const float* w3, int g) {
    return (g == 0) ? w0 : ((g == 1) ? w1 : ((g == 2) ? w2 : w3));
}

// ---------------------------------------------------------------------------
// prep: 64 blocks = (g, kt 128-code tile, quarter q).
// ---------------------------------------------------------------------------
__global__ void gsm4_prep_kernel(const float* __restrict__ w0, const float* __restrict__ w1,
                                 const float* __restrict__ w2, const float* __restrict__ w3) {
    extern __shared__ float sw[];                  // [128][132] raw f32 tile
    const int bx = blockIdx.x;
    const int g  = bx >> 4;
    const int kt = (bx >> 2) & 3;
    const int q  = bx & 3;
    const int tid = threadIdx.x;
    const float* W = pick_w(w0, w1, w2, w3, g) + (size_t)kt * 128 * SDQ;

    #pragma unroll
    for (int j = 0; j < 16; j++) {
        int i = tid + 256 * j;
        int k = i >> 5, dq = (i & 31) * 4;
        *(float4*)(sw + k * 132 + dq) = *(const float4*)(W + (size_t)k * SDQ + dq);
    }
    if (bx == 0) {
        #pragma unroll
        for (int j = 0; j < 8; j++) g_avg[tid + 256 * j] = 0.f;
        if (tid == 0) g_ctr = 0u;
    }
    __syncthreads();

    if (tid < 32) {
        int k = 32 * q + tid;
        const float* r = sw + k * 132;
        float s0 = 0.f, s1 = 0.f, s2 = 0.f, s3 = 0.f;
        #pragma unroll 8
        for (int d = 0; d < SDQ; d += 4) {
            s0 = fmaf(r[d], r[d], s0);
            s1 = fmaf(r[d + 1], r[d + 1], s1);
            s2 = fmaf(r[d + 2], r[d + 2], s2);
            s3 = fmaf(r[d + 3], r[d + 3], s3);
        }
        g_csq[g * KQ + kt * 128 + k] = (s0 + s1) + (s2 + s3);
    }

    // g_w1f: frag flocal = c_l*32 + kg*8 + tg, tg = wq1*2 + t.
    // code label: k_local = c_l*64 + (tg>>1)*16 + (lg>>1)*4 + (tg&1)*2 + (lg&1)
    #pragma unroll
    for (int j = 0; j < 8; j++) {
        int idx = q * 2048 + tid + 256 * j;
        int flocal = idx >> 7;
        int within = idx & 127;
        int lane = within >> 2, jj = within & 3;
        int lg = lane >> 2, lt = lane & 3;
        int c_l = flocal >> 5, kg = (flocal >> 3) & 3, tg = flocal & 7;
        int k_local = c_l * 64 + (tg >> 1) * 16 + (lg >> 1) * 4 + (tg & 1) * 2 + (lg & 1);
        int o = kg * 16 + lt * 4 + jj;
        int d0 = (o >> 4) * 32 + inv16(o & 15);
        g_w1f[(size_t)g * 32768 + (size_t)(kt * 64 + flocal) * 128 + within] =
            pk(sw[k_local * 132 + d0], sw[k_local * 132 + d0 + 1]);
    }
    // g_wtf: frag flocal = c_l*32 + g2*16 + wqf*8 + t; word o -> codes (2o,2o+1)
    #pragma unroll
    for (int j = 0; j < 8; j++) {
        int idx = q * 2048 + tid + 256 * j;
        int flocal = idx >> 7;
        int within = idx & 127;
        int lane = within >> 2, jj = within & 3;
        int lg = lane >> 2, lt = lane & 3;
        int c_l = flocal >> 5, g2 = (flocal >> 4) & 1, wqf = (flocal >> 3) & 1, t = flocal & 7;
        int d = wqf * 64 + t * 8 + lg;
        int o = c_l * 32 + g2 * 16 + lt * 4 + jj;
        g_wtf[(size_t)g * 32768 + (size_t)(kt * 64 + flocal) * 128 + within] =
            pk(sw[(2 * o) * 132 + d], sw[(2 * o + 1) * 132 + d]);
    }
}

// ---------------------------------------------------------------------------
// fused main kernel: CTA = (group g, 64-token tile), 256 threads / 8 warps
// GEMM1 warp: (wm1 = wid>>2, wq1 = wid&3) -> 32 rows x 16 codes/chunk
// GEMM2 warp: (wm2 = wid>>2, wq2 = wid&3) -> 32 rows x 32 d
// ---------------------------------------------------------------------------
__global__ __launch_bounds__(NTHR, 2)
void gsm4_fused_kernel(const float* __restrict__ x,
                       const float* __restrict__ gum,
                       float* __restrict__ out,
                       int do_perp) {
    extern __shared__ char smc[];
    const int g  = blockIdx.y;
    const int n0 = blockIdx.x * TM;
    const int b  = n0 / TQ;
    const int t0 = n0 % TQ;

    const int tid  = threadIdx.x;
    const int wid  = tid >> 5;
    const int lane = tid & 31;
    const int lg   = lane >> 2;
    const int lt   = lane & 3;
    const int wm1  = wid >> 2;
    const int wq1  = wid & 3;
    const int M1   = wm1 * 32;
    const int wq2  = wid & 3;
    const int M2   = (wid >> 2) * 32;

    uint32_t* sP   = (uint32_t*)(smc + OFF_P);
    float* sX      = (float*)(smc + OFF_P);        // overlay (stride SXS)
    float* sCsq    = (float*)(smc + OFF_CSQ);
    float* sRs     = (float*)(smc + OFF_RS);
    float* sRinv   = (float*)(smc + OFF_RI);

    // prologue --------------------------------------------------------------
    sCsq[tid]       = (0.5f * L2E) * g_csq[g * KQ + tid];
    sCsq[tid + 256] = (0.5f * L2E) * g_csq[g * KQ + tid + 256];
    if (tid < TM) sRs[tid] = 0.f;

    {
        const float* xb = x + ((size_t)(b * 512 + g * SDQ)) * TQ + t0;
        #pragma unroll
        for (int j = 0; j < 8; j++) {
            int i = tid + NTHR * j;
            int d = i >> 4, mq = (i & 15) * 4;
            *(float4*)(sX + d * SXS + mq) = *(const float4*)(xb + (size_t)d * TQ + mq);
        }
    }
    __syncthreads();

    // A fragments (GEMM1): 2 m-tiles x 8 k16-steps x 4 half2 regs -----------
    uint32_t af[2][8][4];
    #pragma unroll
    for (int mt = 0; mt < 2; mt++) {
        const int mb = M1 + mt * 16;
        #pragma unroll
        for (int s = 0; s < 8; s++) {
            int dbs = 16 * s + 2 * lt;
            af[mt][s][0] = pk(sX[dbs * SXS + mb + lg],           sX[(dbs + 1) * SXS + mb + lg]);
            af[mt][s][1] = pk(sX[dbs * SXS + mb + lg + 8],       sX[(dbs + 1) * SXS + mb + lg + 8]);
            af[mt][s][2] = pk(sX[(dbs + 8) * SXS + mb + lg],     sX[(dbs + 9) * SXS + mb + lg]);
            af[mt][s][3] = pk(sX[(dbs + 8) * SXS + mb + lg + 8], sX[(dbs + 9) * SXS + mb + lg + 8]);
        }
    }
    __syncthreads();                                // sX dead -> sP region

    // gumbel base: row M1+lg, codes wq1*16 + lt*4 (16B contiguous per row)
    const float* gmr = gum + ((size_t)g * NTOK + n0 + M1 + lg) * KQ + wq1 * 16 + lt * 4;
    const uint32_t* w1f = g_w1f + (size_t)g * 32768 + (size_t)(wq1 * 2) * 128 + lane * 4;
    const uint32_t* wtf = g_wtf + (size_t)g * 32768 + (size_t)(wq2 * 4) * 128 + lane * 4;

    // ---------------- GEMM1 + fused exp (ex2): barrier-free ----------------
    float rs[4] = {0.f, 0.f, 0.f, 0.f};
    for (int c = 0; c < 8; c++) {
        float4 cs = *(const float4*)(sCsq + c * 64 + wq1 * 16 + lt * 4);

        float acc[2][2][4];
        #pragma unroll
        for (int mt = 0; mt < 2; mt++)
            #pragma unroll
            for (int t = 0; t < 2; t++)
                #pragma unroll
                for (int e = 0; e < 4; e++) acc[mt][t][e] = 0.f;

        #pragma unroll
        for (int kg = 0; kg < 4; kg++) {
            #pragma unroll
            for (int t = 0; t < 2; t++) {
                uint4 B = *(const uint4*)(w1f + (size_t)((c * 4 + kg) * 8 + t) * 128);
                #pragma unroll
                for (int mt = 0; mt < 2; mt++) {
                    mma_f16(acc[mt][t], af[mt][2 * kg][0], af[mt][2 * kg][1],
                            af[mt][2 * kg][2], af[mt][2 * kg][3], B.x, B.y);
                    mma_f16(acc[mt][t], af[mt][2 * kg + 1][0], af[mt][2 * kg + 1][1],
                            af[mt][2 * kg + 1][2], af[mt][2 * kg + 1][3], B.z, B.w);
                }
            }
        }
        // fused exp epilogue: label order within float4 = (t0e0,t0e1,t1e0,t1e1)
        #pragma unroll
        for (int mt = 0; mt < 2; mt++) {
            const float* pR = gmr + (size_t)(mt * 16) * KQ + c * 64;
            float4 gA = *(const float4*)(pR);
            float4 gB = *(const float4*)(pR + 8 * KQ);
            float p00 = ex2(fmaf(acc[mt][0][0], L2E, fmaf(gA.x, HL2E, -cs.x)));
            float p01 = ex2(fmaf(acc[mt][0][1], L2E, fmaf(gA.y, HL2E, -cs.y)));
            float p02 = ex2(fmaf(acc[mt][1][0], L2E, fmaf(gA.z, HL2E, -cs.z)));
            float p03 = ex2(fmaf(acc[mt][1][1], L2E, fmaf(gA.w, HL2E, -cs.w)));
            float p10 = ex2(fmaf(acc[mt][0][2], L2E, fmaf(gB.x, HL2E, -cs.x)));
            float p11 = ex2(fmaf(acc[mt][0][3], L2E, fmaf(gB.y, HL2E, -cs.y)));
            float p12 = ex2(fmaf(acc[mt][1][2], L2E, fmaf(gB.z, HL2E, -cs.z)));
            float p13 = ex2(fmaf(acc[mt][1][3], L2E, fmaf(gB.w, HL2E, -cs.w)));
            rs[2 * mt]     += (p00 + p01) + (p02 + p03);
            rs[2 * mt + 1] += (p10 + p11) + (p12 + p13);
            const int wbase = (M1 + mt * 16 + lg) * PSW + c * 32 + wq1 * 8 + lt * 2;
            *(uint2*)(sP + wbase)           = make_uint2(pk(p00, p01), pk(p02, p03));
            *(uint2*)(sP + wbase + 8 * PSW) = make_uint2(pk(p10, p11), pk(p12, p13));
        }
    }
    // rowsum partials: reduce over lt lanes, atomics at lt==0 ---------------
    #pragma unroll
    for (int r = 0; r < 4; r++) {
        rs[r] += __shfl_xor_sync(0xffffffffu, rs[r], 1);
        rs[r] += __shfl_xor_sync(0xffffffffu, rs[r], 2);
    }
    if (lt == 0) {
        atomicAdd(&sRs[M1 + lg], rs[0]);
        atomicAdd(&sRs[M1 + lg + 8], rs[1]);
        atomicAdd(&sRs[M1 + 16 + lg], rs[2]);
        atomicAdd(&sRs[M1 + 16 + lg + 8], rs[3]);
    }
    __syncthreads();                                // sP complete (cross-warp reads)

    // ---------------- GEMM2: 32 rows x 32 d per warp -----------------------
    float qa[2][4][4];
    #pragma unroll
    for (int mt = 0; mt < 2; mt++)
        #pragma unroll
        for (int t = 0; t < 4; t++)
            #pragma unroll
            for (int e = 0; e < 4; e++) qa[mt][t][e] = 0.f;

    for (int c = 0; c < 8; c++) {
        #pragma unroll
        for (int g2 = 0; g2 < 2; g2++) {
            const int abase = (c * 2 + g2) * 16 + 4 * lt;
            uint4 U0 = *(const uint4*)(sP + (M2 + lg) * PSW + abase);
            uint4 U1 = *(const uint4*)(sP + (M2 + lg + 8) * PSW + abase);
            uint4 U2 = *(const uint4*)(sP + (M2 + lg + 16) * PSW + abase);
            uint4 U3 = *(const uint4*)(sP + (M2 + lg + 24) * PSW + abase);
            #pragma unroll
            for (int t = 0; t < 4; t++) {
                uint4 B = *(const uint4*)(wtf + (size_t)((c * 2 + g2) * 16 + t) * 128);
                mma_f16(qa[0][t], U0.x, U1.x, U0.y, U1.y, B.x, B.y);
                mma_f16(qa[0][t], U0.z, U1.z, U0.w, U1.w, B.z, B.w);
                mma_f16(qa[1][t], U2.x, U3.x, U2.y, U3.y, B.x, B.y);
                mma_f16(qa[1][t], U2.z, U3.z, U2.w, U3.w, B.z, B.w);
            }
        }
    }
    __syncthreads();                                // rowsum atomics visible
    if (tid < TM) sRinv[tid] = 1.0f / sRs[tid];
    __syncthreads();

    // avg_probs: thread tid owns codes (2*tid, 2*tid+1) ---------------------
    {
        float s0 = 0.f, s1 = 0.f;
        #pragma unroll 8
        for (int r = 0; r < TM; r++) {
            uint32_t u = sP[r * PSW + tid];
            __half2 h = *reinterpret_cast<__half2*>(&u);
            float2 f = __half22float2(h);
            float ri = sRinv[r];
            s0 = fmaf(f.x, ri, s0);
            s1 = fmaf(f.y, ri, s1);
        }
        atomicAdd(&g_avg[g * KQ + 2 * tid], s0);
        atomicAdd(&g_avg[g * KQ + 2 * tid + 1], s1);
    }
    __syncthreads();                                // sP free for staging

    // epilogue: normalize, single staging pass, coalesced STG.128 -----------
    {
        float* stage = (float*)(smc + OFF_P);       // [128 d][SXS]
        float rv[2][2];
        #pragma unroll
        for (int mt = 0; mt < 2; mt++) {
            rv[mt][0] = sRinv[M2 + mt * 16 + lg];
            rv[mt][1] = sRinv[M2 + mt * 16 + lg + 8];
        }
        #pragma unroll
        for (int mt = 0; mt < 2; mt++) {
            #pragma unroll
            for (int t = 0; t < 4; t++) {
                int d = wq2 * 32 + t * 8 + 2 * lt;
                int m = M2 + mt * 16 + lg;
                stage[d * SXS + m]           = qa[mt][t][0] * rv[mt][0];
                stage[(d + 1) * SXS + m]     = qa[mt][t][1] * rv[mt][0];
                stage[d * SXS + m + 8]       = qa[mt][t][2] * rv[mt][1];
                stage[(d + 1) * SXS + m + 8] = qa[mt][t][3] * rv[mt][1];
            }
        }
        __syncthreads();
        float* ob = out + ((size_t)(b * 512 + g * SDQ)) * TQ + t0;
        #pragma unroll
        for (int j = 0; j < 8; j++) {
            int i = tid + NTHR * j;
            int d = i >> 4, mq = (i & 15) * 4;
            float4 v = *(const float4*)(stage + d * SXS + mq);
            *(float4*)(ob + (size_t)d * TQ + mq) = v;
        }
    }

    // ---------------- perp: last CTA reduces g_avg -------------------------
    if (do_perp) {
        __shared__ unsigned s_last;
        __shared__ float se[8];
        __threadfence();
        __syncthreads();
        if (tid == 0)
            s_last = (atomicAdd(&g_ctr, 1u) == gridDim.x * gridDim.y - 1u) ? 1u : 0u;
        __syncthreads();
        if (s_last) {
            int gg = tid >> 6;
            int tt = tid & 63;
            float acc = 0.f;
            #pragma unroll
            for (int j = 0; j < 8; j++) {
                float a = g_avg[gg * KQ + tt + 64 * j] * (1.0f / (float)NTOK);
                acc += a * logf(a + 1e-10f);
            }
            #pragma unroll
            for (int o = 16; o; o >>= 1) acc += __shfl_xor_sync(0xffffffffu, acc, o);
            if (lane == 0) se[wid] = acc;
            __syncthreads();
            if (tid == 0) {
                float p = 0.f;
                #pragma unroll
                for (int g2 = 0; g2 < NG; g2++) p += expf(-(se[2 * g2] + se[2 * g2 + 1]));
                out[QUANT_ELEMS] = p;
            }
        }
    }
}

// ---------------------------------------------------------------------------
extern "C" void kernel_launch(void* const* d_in, const int* in_sizes, int n_in,
                              void* d_out, int out_size) {
    const float* x   = (const float*)d_in[0];
    const float* w0  = (const float*)d_in[1];
    const float* w1  = (const float*)d_in[2];
    const float* w2  = (const float*)d_in[3];
    const float* w3  = (const float*)d_in[4];
    const float* gum = (const float*)d_in[5];
    float* out = (float*)d_out;

    cudaFuncSetAttribute(gsm4_prep_kernel,
                         cudaFuncAttributeMaxDynamicSharedMemorySize, 128 * 132 * 4);
    cudaFuncSetAttribute(gsm4_fused_kernel,
                         cudaFuncAttributeMaxDynamicSharedMemorySize, SMEM_BYTES);

    gsm4_prep_kernel<<<64, 256, 128 * 132 * 4>>>(w0, w1, w2, w3);

    dim3 grid(NTOK / TM, NG);
    int do_perp = (out_size > QUANT_ELEMS) ? 1 : 0;
    gsm4_fused_kernel<<<grid, NTHR, SMEM_BYTES>>>(x, gum, out, do_perp);
}

// round 16
// speedup vs baseline: 1.4024x; 1.4024x over previous
#include <cuda_runtime.h>
#include <cuda_fp16.h>
#include <cstdint>

// ---------------------------------------------------------------------------
// GumbelSoftmaxModule4 v16: v14 (best) + barrier-schedule trim.
//   rinv computed right after the single post-GEMM1 barrier; GEMM2 and
//   avg_probs run back-to-back with no intervening barrier (both read-only
//   on sP). 5 -> 4 barriers in the back half.
// ---------------------------------------------------------------------------

namespace {
constexpr int KQ = 512, NG = 4, SDQ = 128, BQ = 16, TQ = 2048;
constexpr int NTOK = BQ * TQ;            // 32768
constexpr int TM   = 64;                 // tokens per CTA
constexpr int NTHR = 256;                // 8 warps
constexpr int PSW  = 272;                // sP row stride (uint32 words)
constexpr int SXS  = 68;                 // X / stage row stride (f32)
constexpr int OFF_P   = 0;                          // sP: 64*272*4 = 69632
constexpr int OFF_CSQ = 69632;                      // 512 f32 (pre-scaled)
constexpr int OFF_RS  = OFF_CSQ + 2048;             // 64 f32
constexpr int OFF_RI  = OFF_RS + 256;               // 64 f32
constexpr int SMEM_BYTES = OFF_RI + 256;            // 72192 -> occ 2
constexpr int QUANT_ELEMS = BQ * 512 * TQ;
constexpr float L2E  = 1.4426950408889634f;
constexpr float HL2E = 0.7213475204444817f;
}

__device__ float g_csq[NG * KQ];
__device__ float g_avg[NG * KQ];
__device__ unsigned int g_ctr;
// fragment-major: [g][frag 0..255][128 words]; frag = 512B = one warp LDG.128
__device__ __align__(16) uint32_t g_w1f[NG * 256 * 128];
__device__ __align__(16) uint32_t g_wtf[NG * 256 * 128];

// ------------------------------ helpers ------------------------------------
__device__ __forceinline__ int inv16(int o) {      // GEMM1 d-interleave only
    return (((o >> 1) & 1) << 4) | ((o & 1) << 3) | (((o >> 2) & 3) << 1);
}
__device__ __forceinline__ uint32_t pk(float lo, float hi) {
    __half2 h = __floats2half2_rn(lo, hi);
    return *reinterpret_cast<uint32_t*>(&h);
}
__device__ __forceinline__ float ex2(float y) {    // 2^y via MUFU
    float r;
    asm("ex2.approx.f32 %0, %1;" : "=f"(r) : "f"(y));
    return r;
}
__device__ __forceinline__ void mma_f16(float* c,
                                        uint32_t a0, uint32_t a1, uint32_t a2, uint32_t a3,
                                        uint32_t b0, uint32_t b1) {
    asm volatile(
        "mma.sync.aligned.m16n8k16.row.col.f32.f16.f16.f32 "
        "{%0,%1,%2,%3}, {%4,%5,%6,%7}, {%8,%9}, {%0,%1,%2,%3};\n"
        : "+f"(c[0]), "+f"(c[1]), "+f"(c[2]), "+f"(c[3])
        : "r"(a0), "r"(a1), "r"(a2), "r"(a3), "r"(b0), "r"(b1));
}
__device__ __forceinline__ const float* pick_w(const float* w0, const float* w1,
                                               const float* w2, const float* w3, int g) {
    return (g == 0) ? w0 : ((g == 1) ? w1 : ((g == 2) ? w2 : w3));
}

// ---------------------------------------------------------------------------
// prep: 64 blocks = (g, kt 128-code tile, quarter q).  (v13/v14 layout)
// ---------------------------------------------------------------------------
__global__ void gsm4_prep_kernel(const float* __restrict__ w0, const float* __restrict__ w1,
                                 const float* __restrict__ w2, const float* __restrict__ w3) {
    extern __shared__ float sw[];                  // [128][132] raw f32 tile
    const int bx = blockIdx.x;
    const int g  = bx >> 4;
    const int kt = (bx >> 2) & 3;
    const int q  = bx & 3;
    const int tid = threadIdx.x;
    const float* W = pick_w(w0, w1, w2, w3, g) + (size_t)kt * 128 * SDQ;

    #pragma unroll
    for (int j = 0; j < 16; j++) {
        int i = tid + 256 * j;
        int k = i >> 5, dq = (i & 31) * 4;
        *(float4*)(sw + k * 132 + dq) = *(const float4*)(W + (size_t)k * SDQ + dq);
    }
    if (bx == 0) {
        #pragma unroll
        for (int j = 0; j < 8; j++) g_avg[tid + 256 * j] = 0.f;
        if (tid == 0) g_ctr = 0u;
    }
    __syncthreads();

    if (tid < 32) {
        int k = 32 * q + tid;
        const float* r = sw + k * 132;
        float s0 = 0.f, s1 = 0.f, s2 = 0.f, s3 = 0.f;
        #pragma unroll 8
        for (int d = 0; d < SDQ; d += 4) {
            s0 = fmaf(r[d], r[d], s0);
            s1 = fmaf(r[d + 1], r[d + 1], s1);
            s2 = fmaf(r[d + 2], r[d + 2], s2);
            s3 = fmaf(r[d + 3], r[d + 3], s3);
        }
        g_csq[g * KQ + kt * 128 + k] = (s0 + s1) + (s2 + s3);
    }

    // g_w1f: frag flocal = c_l*32 + kg*8 + tg; lane's n-pos = lg.
    #pragma unroll
    for (int j = 0; j < 8; j++) {
        int idx = q * 2048 + tid + 256 * j;
        int flocal = idx >> 7;
        int within = idx & 127;
        int lane = within >> 2, jj = within & 3;
        int lg = lane >> 2, lt = lane & 3;
        int c_l = flocal >> 5, kg = (flocal >> 3) & 3, tg = flocal & 7;
        int k_local = c_l * 64 + (tg >> 2) * 32 + (lg >> 1) * 8 + (tg & 3) * 2 + (lg & 1);
        int o = kg * 16 + lt * 4 + jj;
        int d0 = (o >> 4) * 32 + inv16(o & 15);
        g_w1f[(size_t)g * 32768 + (size_t)(kt * 64 + flocal) * 128 + within] =
            pk(sw[k_local * 132 + d0], sw[k_local * 132 + d0 + 1]);
    }
    // g_wtf: frag flocal = c_l*32 + g2*16 + wqf*8 + t; word o -> codes (2o,2o+1)
    #pragma unroll
    for (int j = 0; j < 8; j++) {
        int idx = q * 2048 + tid + 256 * j;
        int flocal = idx >> 7;
        int within = idx & 127;
        int lane = within >> 2, jj = within & 3;
        int lg = lane >> 2, lt = lane & 3;
        int c_l = flocal >> 5, g2 = (flocal >> 4) & 1, wqf = (flocal >> 3) & 1, t = flocal & 7;
        int d = wqf * 64 + t * 8 + lg;
        int o = c_l * 32 + g2 * 16 + lt * 4 + jj;
        g_wtf[(size_t)g * 32768 + (size_t)(kt * 64 + flocal) * 128 + within] =
            pk(sw[(2 * o) * 132 + d], sw[(2 * o + 1) * 132 + d]);
    }
}

// ---------------------------------------------------------------------------
// fused main kernel: CTA = (group g, 64-token tile), 256 threads / 8 warps
// GEMM1 warp: (wm = wid>>1, wq = wid&1)  -> 16 rows x 32 codes/chunk
// GEMM2 warp: (wm2 = wid>>2, wq2 = wid&3) -> 32 rows x 32 d
// ---------------------------------------------------------------------------
__global__ __launch_bounds__(NTHR, 2)
void gsm4_fused_kernel(const float* __restrict__ x,
                       const float* __restrict__ gum,
                       float* __restrict__ out,
                       int do_perp) {
    extern __shared__ char smc[];
    const int g  = blockIdx.y;
    const int n0 = blockIdx.x * TM;
    const int b  = n0 / TQ;
    const int t0 = n0 % TQ;

    const int tid  = threadIdx.x;
    const int wid  = tid >> 5;
    const int lane = tid & 31;
    const int lg   = lane >> 2;
    const int lt   = lane & 3;
    const int wm   = wid >> 1;
    const int wq   = wid & 1;
    const int m0   = wm * 16;
    const int wm2  = wid >> 2;
    const int wq2  = wid & 3;
    const int M2   = wm2 * 32;

    uint32_t* sP   = (uint32_t*)(smc + OFF_P);
    float* sX      = (float*)(smc + OFF_P);        // overlay (stride SXS)
    float* sCsq    = (float*)(smc + OFF_CSQ);
    float* sRs     = (float*)(smc + OFF_RS);
    float* sRinv   = (float*)(smc + OFF_RI);

    // prologue --------------------------------------------------------------
    sCsq[tid]       = (0.5f * L2E) * g_csq[g * KQ + tid];
    sCsq[tid + 256] = (0.5f * L2E) * g_csq[g * KQ + tid + 256];
    if (tid < TM) sRs[tid] = 0.f;

    {
        const float* xb = x + ((size_t)(b * 512 + g * SDQ)) * TQ + t0;
        #pragma unroll
        for (int j = 0; j < 8; j++) {
            int i = tid + NTHR * j;
            int d = i >> 4, mq = (i & 15) * 4;
            *(float4*)(sX + d * SXS + mq) = *(const float4*)(xb + (size_t)d * TQ + mq);
        }
    }
    __syncthreads();

    // A fragments (GEMM1): 8 k16-steps x 4 half2 regs -----------------------
    uint32_t af[8][4];
    #pragma unroll
    for (int s = 0; s < 8; s++) {
        int dbs = 16 * s + 2 * lt;
        af[s][0] = pk(sX[dbs * SXS + m0 + lg],           sX[(dbs + 1) * SXS + m0 + lg]);
        af[s][1] = pk(sX[dbs * SXS + m0 + lg + 8],       sX[(dbs + 1) * SXS + m0 + lg + 8]);
        af[s][2] = pk(sX[(dbs + 8) * SXS + m0 + lg],     sX[(dbs + 9) * SXS + m0 + lg]);
        af[s][3] = pk(sX[(dbs + 8) * SXS + m0 + lg + 8], sX[(dbs + 9) * SXS + m0 + lg + 8]);
    }
    __syncthreads();                                // sX dead -> sP region

    // contiguous 32B gumbel base per thread (codes wq*32+lt*8 .. +7)
    const float* gmr = gum + ((size_t)g * NTOK + n0 + m0 + lg) * KQ + wq * 32 + lt * 8;
    const uint32_t* w1f = g_w1f + (size_t)g * 32768 + (size_t)(wq * 4) * 128 + lane * 4;
    const uint32_t* wtf = g_wtf + (size_t)g * 32768 + (size_t)(wq2 * 4) * 128 + lane * 4;

    // ---------------- GEMM1 + fused exp (ex2): barrier-free ----------------
    float rs0 = 0.f, rs1 = 0.f;
    for (int c = 0; c < 8; c++) {
        float4 csa = *(const float4*)(sCsq + c * 64 + wq * 32 + lt * 8);
        float4 csb = *(const float4*)(sCsq + c * 64 + wq * 32 + lt * 8 + 4);
        const float* pA = gmr + c * 64;
        float4 ga0 = *(const float4*)(pA);
        float4 ga1 = *(const float4*)(pA + 4);
        float4 gb0 = *(const float4*)(pA + 8 * KQ);
        float4 gb1 = *(const float4*)(pA + 8 * KQ + 4);

        float acc[4][4];
        #pragma unroll
        for (int t = 0; t < 4; t++)
            #pragma unroll
            for (int e = 0; e < 4; e++) acc[t][e] = 0.f;

        #pragma unroll
        for (int kg = 0; kg < 4; kg++) {
            #pragma unroll
            for (int t = 0; t < 4; t++) {
                uint4 B = *(const uint4*)(w1f + (size_t)((c * 4 + kg) * 8 + t) * 128);
                mma_f16(acc[t], af[2 * kg][0], af[2 * kg][1], af[2 * kg][2], af[2 * kg][3], B.x, B.y);
                mma_f16(acc[t], af[2 * kg + 1][0], af[2 * kg + 1][1], af[2 * kg + 1][2], af[2 * kg + 1][3], B.z, B.w);
            }
        }
        const float csv[8] = {csa.x, csa.y, csa.z, csa.w, csb.x, csb.y, csb.z, csb.w};
        const float gav[8] = {ga0.x, ga0.y, ga0.z, ga0.w, ga1.x, ga1.y, ga1.z, ga1.w};
        const float gbv[8] = {gb0.x, gb0.y, gb0.z, gb0.w, gb1.x, gb1.y, gb1.z, gb1.w};
        uint4 ua, ub;
        uint32_t* pu_a = &ua.x;
        uint32_t* pu_b = &ub.x;
        #pragma unroll
        for (int t = 0; t < 4; t++) {
            float p0v = ex2(fmaf(acc[t][0], L2E, fmaf(gav[2 * t],     HL2E, -csv[2 * t])));
            float p1v = ex2(fmaf(acc[t][1], L2E, fmaf(gav[2 * t + 1], HL2E, -csv[2 * t + 1])));
            float p2v = ex2(fmaf(acc[t][2], L2E, fmaf(gbv[2 * t],     HL2E, -csv[2 * t])));
            float p3v = ex2(fmaf(acc[t][3], L2E, fmaf(gbv[2 * t + 1], HL2E, -csv[2 * t + 1])));
            rs0 += p0v + p1v;
            rs1 += p2v + p3v;
            pu_a[t] = pk(p0v, p1v);
            pu_b[t] = pk(p2v, p3v);
        }
        const int wbase = (m0 + lg) * PSW + c * 32 + wq * 16 + 4 * lt;
        *(uint4*)(sP + wbase)           = ua;
        *(uint4*)(sP + wbase + 8 * PSW) = ub;
    }
    // rowsum partials ------------------------------------------------------
    rs0 += __shfl_xor_sync(0xffffffffu, rs0, 1);
    rs0 += __shfl_xor_sync(0xffffffffu, rs0, 2);
    rs1 += __shfl_xor_sync(0xffffffffu, rs1, 1);
    rs1 += __shfl_xor_sync(0xffffffffu, rs1, 2);
    if (lt == 0) {
        atomicAdd(&sRs[m0 + lg], rs0);
        atomicAdd(&sRs[m0 + lg + 8], rs1);
    }
    __syncthreads();                    // sP complete + all rowsums visible

    // rinv right away (overlaps nothing downstream on the critical path) ----
    if (tid < TM) sRinv[tid] = 1.0f / sRs[tid];
    __syncthreads();                    // rinv visible

    // ---------------- GEMM2: 32 rows x 32 d per warp -----------------------
    float qa[2][4][4];
    #pragma unroll
    for (int mt = 0; mt < 2; mt++)
        #pragma unroll
        for (int t = 0; t < 4; t++)
            #pragma unroll
            for (int e = 0; e < 4; e++) qa[mt][t][e] = 0.f;

    for (int c = 0; c < 8; c++) {
        #pragma unroll
        for (int g2 = 0; g2 < 2; g2++) {
            const int abase = (c * 2 + g2) * 16 + 4 * lt;
            uint4 U0 = *(const uint4*)(sP + (M2 + lg) * PSW + abase);
            uint4 U1 = *(const uint4*)(sP + (M2 + lg + 8) * PSW + abase);
            uint4 U2 = *(const uint4*)(sP + (M2 + lg + 16) * PSW + abase);
            uint4 U3 = *(const uint4*)(sP + (M2 + lg + 24) * PSW + abase);
            #pragma unroll
            for (int t = 0; t < 4; t++) {
                uint4 B = *(const uint4*)(wtf + (size_t)((c * 2 + g2) * 16 + t) * 128);
                mma_f16(qa[0][t], U0.x, U1.x, U0.y, U1.y, B.x, B.y);
                mma_f16(qa[0][t], U0.z, U1.z, U0.w, U1.w, B.z, B.w);
                mma_f16(qa[1][t], U2.x, U3.x, U2.y, U3.y, B.x, B.y);
                mma_f16(qa[1][t], U2.z, U3.z, U2.w, U3.w, B.z, B.w);
            }
        }
    }

    // avg_probs: thread tid owns codes (2*tid, 2*tid+1) — no barrier needed:
    // both this and GEMM2 are read-only on sP; rinv already visible.
    {
        float s0 = 0.f, s1 = 0.f;
        #pragma unroll 8
        for (int r = 0; r < TM; r++) {
            uint32_t u = sP[r * PSW + tid];
            __half2 h = *reinterpret_cast<__half2*>(&u);
            float2 f = __half22float2(h);
            float ri = sRinv[r];
            s0 = fmaf(f.x, ri, s0);
            s1 = fmaf(f.y, ri, s1);
        }
        atomicAdd(&g_avg[g * KQ + 2 * tid], s0);
        atomicAdd(&g_avg[g * KQ + 2 * tid + 1], s1);
    }
    __syncthreads();                    // all sP reads done -> staging may overwrite

    // epilogue: normalize, single staging pass, coalesced STG.128 -----------
    {
        float* stage = (float*)(smc + OFF_P);       // [128 d][SXS]
        float rv[2][2];
        #pragma unroll
        for (int mt = 0; mt < 2; mt++) {
            rv[mt][0] = sRinv[M2 + mt * 16 + lg];
            rv[mt][1] = sRinv[M2 + mt * 16 + lg + 8];
        }
        #pragma unroll
        for (int mt = 0; mt < 2; mt++) {
            #pragma unroll
            for (int t = 0; t < 4; t++) {
                int d = wq2 * 32 + t * 8 + 2 * lt;
                int m = M2 + mt * 16 + lg;
                stage[d * SXS + m]           = qa[mt][t][0] * rv[mt][0];
                stage[(d + 1) * SXS + m]     = qa[mt][t][1] * rv[mt][0];
                stage[d * SXS + m + 8]       = qa[mt][t][2] * rv[mt][1];
                stage[(d + 1) * SXS + m + 8] = qa[mt][t][3] * rv[mt][1];
            }
        }
        __syncthreads();
        float* ob = out + ((size_t)(b * 512 + g * SDQ)) * TQ + t0;
        #pragma unroll
        for (int j = 0; j < 8; j++) {
            int i = tid + NTHR * j;
            int d = i >> 4, mq = (i & 15) * 4;
            float4 v = *(const float4*)(stage + d * SXS + mq);
            *(float4*)(ob + (size_t)d * TQ + mq) = v;
        }
    }

    // ---------------- perp: last CTA reduces g_avg -------------------------
    if (do_perp) {
        __shared__ unsigned s_last;
        __shared__ float se[8];
        __threadfence();
        __syncthreads();
        if (tid == 0)
            s_last = (atomicAdd(&g_ctr, 1u) == gridDim.x * gridDim.y - 1u) ? 1u : 0u;
        __syncthreads();
        if (s_last) {
            int gg = tid >> 6;
            int tt = tid & 63;
            float acc = 0.f;
            #pragma unroll
            for (int j = 0; j < 8; j++) {
                float a = g_avg[gg * KQ + tt + 64 * j] * (1.0f / (float)NTOK);
                acc += a * logf(a + 1e-10f);
            }
            #pragma unroll
            for (int o = 16; o; o >>= 1) acc += __shfl_xor_sync(0xffffffffu, acc, o);
            if (lane == 0) se[wid] = acc;
            __syncthreads();
            if (tid == 0) {
                float p = 0.f;
                #pragma unroll
                for (int g2 = 0; g2 < NG; g2++) p += expf(-(se[2 * g2] + se[2 * g2 + 1]));
                out[QUANT_ELEMS] = p;
            }
        }
    }
}

// ---------------------------------------------------------------------------
extern "C" void kernel_launch(void* const* d_in, const int* in_sizes, int n_in,
                              void* d_out, int out_size) {
    const float* x   = (const float*)d_in[0];
    const float* w0  = (const float*)d_in[1];
    const float* w1  = (const float*)d_in[2];
    const float* w2  = (const float*)d_in[3];
    const float* w3  = (const float*)d_in[4];
    const float* gum = (const float*)d_in[5];
    float* out = (float*)d_out;

    cudaFuncSetAttribute(gsm4_prep_kernel,
                         cudaFuncAttributeMaxDynamicSharedMemorySize, 128 * 132 * 4);
    cudaFuncSetAttribute(gsm4_fused_kernel,
                         cudaFuncAttributeMaxDynamicSharedMemorySize, SMEM_BYTES);

    gsm4_prep_kernel<<<64, 256, 128 * 132 * 4>>>(w0, w1, w2, w3);

    dim3 grid(NTOK / TM, NG);
    int do_perp = (out_size > QUANT_ELEMS) ? 1 : 0;
    gsm4_fused_kernel<<<grid, NTHR, SMEM_BYTES>>>(x, gum, out, do_perp);
}